// round 1
// baseline (speedup 1.0000x reference)
#include <cuda_runtime.h>
#include <cuda_bf16.h>

#define GSZ 64

// 4 lanes (a quad) cooperate on one point:
//   lane lx in [0,4) loads knot float4 at x-offset lx of each of the 16 (z,y)
//   rows. Within one warp LDG.128 instruction, each quad's 4 lanes cover one
//   contiguous 64B row -> minimal L1 wavefronts per instruction.
// Quad-reduce (2x shfl.bfly on 4 floats), lane 0 stores float4 (coalesced).
__global__ void __launch_bounds__(256) spline3d_kernel(
    const float* __restrict__ coords,
    const float* __restrict__ knots,
    float* __restrict__ out,
    int n)
{
    int tid = blockIdx.x * 256 + threadIdx.x;
    int p  = tid >> 2;   // point index
    int lx = tid & 3;    // x-tap index within the quad
    if (p >= n) return;

    // coords layout [N,3] : (z, y, x)
    float zc = coords[p * 3 + 0];
    float yc = coords[p * 3 + 1];
    float xc = coords[p * 3 + 2];

    float fz = floorf(zc), fy = floorf(yc), fx = floorf(xc);
    int iz = (int)fz, iy = (int)fy, ix = (int)fx;
    float sz = zc - fz, sy = yc - fy, sx = xc - fx;

    // Memory-safety clamp. Input domain guarantees i0 in [1, 60], so this is
    // a no-op for valid data and indices (i0-1 .. i0+2) stay in [0, 63],
    // keeping each row a contiguous 64B span.
    iz = min(max(iz, 1), GSZ - 3);
    iy = min(max(iy, 1), GSZ - 3);
    ix = min(max(ix, 1), GSZ - 3);

    // Catmull-Rom basis (matches reference A = (hermite@catmull)[::-1],
    // c = [1,s,s^2,s^3] @ A):
    //   c0 = s(-0.5 + s(1 - 0.5 s))
    //   c1 = 1 + s^2(-2.5 + 1.5 s)
    //   c2 = s(0.5 + s(2 - 1.5 s))
    //   c3 = s^2(0.5 s - 0.5)
    float cz0 = sz * (-0.5f + sz * (1.0f - 0.5f * sz));
    float cz1 = 1.0f + sz * sz * (-2.5f + 1.5f * sz);
    float cz2 = sz * (0.5f + sz * (2.0f - 1.5f * sz));
    float cz3 = sz * sz * (0.5f * sz - 0.5f);

    float cy0 = sy * (-0.5f + sy * (1.0f - 0.5f * sy));
    float cy1 = 1.0f + sy * sy * (-2.5f + 1.5f * sy);
    float cy2 = sy * (0.5f + sy * (2.0f - 1.5f * sy));
    float cy3 = sy * sy * (0.5f * sy - 0.5f);

    float cx0 = sx * (-0.5f + sx * (1.0f - 0.5f * sx));
    float cx1 = 1.0f + sx * sx * (-2.5f + 1.5f * sx);
    float cx2 = sx * (0.5f + sx * (2.0f - 1.5f * sx));
    float cx3 = sx * sx * (0.5f * sx - 0.5f);

    float czv[4] = {cz0, cz1, cz2, cz3};
    float cyv[4] = {cy0, cy1, cy2, cy3};

    // knots float4 index: z*G*G + y*G + x
    const float4* kb = reinterpret_cast<const float4*>(knots)
                     + ((iz - 1) * GSZ + (iy - 1)) * GSZ + (ix - 1) + lx;

    float ax = 0.0f, ay = 0.0f, az = 0.0f, aw = 0.0f;
#pragma unroll
    for (int zi = 0; zi < 4; zi++) {
#pragma unroll
        for (int yi = 0; yi < 4; yi++) {
            float w = czv[zi] * cyv[yi];
            float4 k = __ldg(kb + zi * (GSZ * GSZ) + yi * GSZ);
            ax = fmaf(w, k.x, ax);
            ay = fmaf(w, k.y, ay);
            az = fmaf(w, k.z, az);
            aw = fmaf(w, k.w, aw);
        }
    }

    // Apply this lane's x-tap weight, then reduce over the quad.
    float wx = (lx == 0) ? cx0 : (lx == 1) ? cx1 : (lx == 2) ? cx2 : cx3;
    ax *= wx; ay *= wx; az *= wx; aw *= wx;

#pragma unroll
    for (int d = 1; d < 4; d <<= 1) {
        ax += __shfl_xor_sync(0xffffffffu, ax, d);
        ay += __shfl_xor_sync(0xffffffffu, ay, d);
        az += __shfl_xor_sync(0xffffffffu, az, d);
        aw += __shfl_xor_sync(0xffffffffu, aw, d);
    }

    if (lx == 0) {
        reinterpret_cast<float4*>(out)[p] = make_float4(ax, ay, az, aw);
    }
}

extern "C" void kernel_launch(void* const* d_in, const int* in_sizes, int n_in,
                              void* d_out, int out_size) {
    const float* coords = (const float*)d_in[0];  // [N,3] f32
    const float* knots  = (const float*)d_in[1];  // [64,64,64,4] f32
    float* out          = (float*)d_out;          // [N,4] f32

    int n = in_sizes[0] / 3;
    long long total = 4LL * n;              // 4 lanes per point
    int blocks = (int)((total + 255) / 256);
    spline3d_kernel<<<blocks, 256>>>(coords, knots, out, n);
}